// round 13
// baseline (speedup 1.0000x reference)
#include <cuda_runtime.h>
#include <mma.h>
#include <math.h>
#include <stdint.h>

using namespace nvcuda;

#define TSZ   512
#define INSZ  1024
#define HIDSZ 1024
#define BH    65536                        // 64*1024
static constexpr size_t TBH = 33554432ull; // 512*64*1024

#define NREC  64                           // recurrence CTAs
#define NS1   80                           // stage1 worker CTAs
#define NTOT  144
#define NTHR  512

// Device-global scratch (no allocations allowed)
__device__ float g_gates[3ull * TBH];           // [gate][t*64+b][hid]
__device__ float g_Wall[6ull * 1048576];        // tf32 W: [hr|hz|hn|ir|iz|in]
__device__ float g_xt[32768ull * 1024];         // tf32 x, time-major [t*64+b][k]
__device__ float g_ht[2][BH];                   // tf32 h ping-pong
__device__ unsigned g_bar_cnt = 0;              // grid barrier (recur CTAs only)
__device__ unsigned g_bar_gen = 0;
__device__ unsigned g_mt_cnt[256];              // stage1 per-mtile counters (monotonic)

// ---------------------------------------------------------------------------
__device__ __forceinline__ unsigned ld_acq(const unsigned* p) {
    unsigned v;
    asm volatile("ld.acquire.gpu.u32 %0, [%1];" : "=r"(v) : "l"(p) : "memory");
    return v;
}
__device__ __forceinline__ void st_rel(unsigned* p, unsigned v) {
    asm volatile("st.release.gpu.u32 [%0], %1;" :: "l"(p), "r"(v) : "memory");
}
__device__ __forceinline__ void red_rel_add(unsigned* p) {
    asm volatile("red.release.gpu.global.add.u32 [%0], %1;" :: "l"(p), "r"(1u) : "memory");
}
__device__ __forceinline__ void cp16(void* sdst, const void* gsrc) {
    unsigned s;
    asm("{ .reg .u64 t; cvta.to.shared.u64 t, %1; cvt.u32.u64 %0, t; }" : "=r"(s) : "l"(sdst));
    asm volatile("cp.async.cg.shared.global [%0], [%1], 16;" :: "r"(s), "l"(gsrc));
}
#define CP_COMMIT() asm volatile("cp.async.commit_group;")
#define CP_WAIT0()  asm volatile("cp.async.wait_group 0;")
#define CP_WAIT1()  asm volatile("cp.async.wait_group 1;")
#define PAIR_BAR(id) asm volatile("bar.sync %0, 64;" :: "r"(id) : "memory")

// ---------------------------------------------------------------------------
// Prep: tf32 weights -> g_Wall[0..5] (hr,hz,hn,ir,iz,in); x tf32 + transpose.
// ---------------------------------------------------------------------------
__global__ void prep_kernel(const float* __restrict__ x,
                            const float* __restrict__ Whr, const float* __restrict__ Whz,
                            const float* __restrict__ Whn, const float* __restrict__ Wir,
                            const float* __restrict__ Wiz, const float* __restrict__ Win) {
    const int bid = blockIdx.x, tid = threadIdx.x;
    if (bid < 6144) {
        int which = bid >> 10;
        int o = (bid & 1023) * 256 + tid;
        const float* src = (which == 0) ? Whr : (which == 1) ? Whz : (which == 2) ? Whn
                         : (which == 3) ? Wir : (which == 4) ? Wiz : Win;
        float4 v = ((const float4*)src)[o];
        v.x = wmma::__float_to_tf32(v.x); v.y = wmma::__float_to_tf32(v.y);
        v.z = wmma::__float_to_tf32(v.z); v.w = wmma::__float_to_tf32(v.w);
        ((float4*)(g_Wall + (size_t)which * 1048576))[o] = v;
    } else {
        int m = bid - 6144;                     // 0..32767, m = t*64+b
        int t = m >> 6, b = m & 63;
        float4 v = ((const float4*)(x + ((size_t)b * TSZ + t) * INSZ))[tid];
        v.x = wmma::__float_to_tf32(v.x); v.y = wmma::__float_to_tf32(v.y);
        v.z = wmma::__float_to_tf32(v.z); v.w = wmma::__float_to_tf32(v.w);
        ((float4*)(g_xt + (size_t)m * 1024))[tid] = v;
    }
}

// ---------------------------------------------------------------------------
// Fused persistent kernel, grid 144 x 512.
//   CTAs [0,64):  recurrence, owner-computes cols [16c,16c+16) of all 3 gates.
//     Phase A: 8 independent kgrp pairs (2 warps, K=128 each), 3-stage cp.async
//     pipeline, pair-local named barriers only. Each kgrp stores its 64x48
//     partial into its own stage region; ONE syncthreads; then all 512 threads
//     do fused 8-way-reduce + GRU pointwise (2 outputs each).
//   CTAs [64,144): stage1 workers (unchanged from R11).
// Recurrence smem (floats): kgrp g region at g*6336:
//   stage s (s=0..2): A[64][20] at +s*2112, B[16][52] at +s*2112+1280
//   partial (post-loop alias): [64][48] at +0
// bias at 50688: [4][16].  Total 50752 fl = 203008 B.
// ---------------------------------------------------------------------------
#define FUSED_SMEM 203008

__global__ __launch_bounds__(NTHR, 1)
void fused_kernel(const float* __restrict__ b_ir, const float* __restrict__ b_hr,
                  const float* __restrict__ b_iz, const float* __restrict__ b_hz,
                  const float* __restrict__ b_in, const float* __restrict__ b_hn,
                  float* __restrict__ out, int write_hfinal) {
    extern __shared__ __align__(16) float sm[];
    const int cta = blockIdx.x;
    const int tid = threadIdx.x;
    const int wid = tid >> 5;

    if (cta >= NREC) {
        // ==================== STAGE1 WORKER ====================
        const int worker = cta - NREC;
        const int mrow = wid & 3;
        const int ncol = wid >> 2;

        for (int u = worker; u < 12288; u += NS1) {
            const int mtile = u / 48;
            const int sub   = u - mtile * 48;
            const int gate  = sub >> 4;
            const int col0s = (sub & 15) << 6;
            const int m0    = mtile << 7;
            const float* Wp = g_Wall + (size_t)(3 + gate) * 1048576;

            wmma::fragment<wmma::accumulator, 16, 16, 8, float> acc0, acc1;
            wmma::fill_fragment(acc0, 0.0f);
            wmma::fill_fragment(acc1, 0.0f);

#define S1_ISSUE(c)                                                             \
            {                                                                   \
                float* As = sm + ((c) & 1) * 6784;                              \
                float* Bs = As + 4608;                                          \
                _Pragma("unroll")                                               \
                for (int q = 0; q < 2; q++) {                                   \
                    int o = tid + q * 512;                                      \
                    int row = o >> 3, c4 = (o & 7) << 2;                        \
                    cp16(As + row * 36 + c4,                                    \
                         g_xt + (size_t)(m0 + row) * 1024 + (c) * 32 + c4);     \
                }                                                               \
                {                                                               \
                    int row = tid >> 4, c4 = (tid & 15) << 2;                   \
                    cp16(Bs + row * 68 + c4,                                    \
                         Wp + (size_t)((c) * 32 + row) * 1024 + col0s + c4);    \
                }                                                               \
            }

            S1_ISSUE(0); CP_COMMIT();
            for (int c = 0; c < 32; c++) {
                CP_WAIT0();
                __syncthreads();
                if (c < 31) { S1_ISSUE(c + 1); CP_COMMIT(); }

                const float* As = sm + (c & 1) * 6784;
                const float* Bs = As + 4608;
#pragma unroll
                for (int kk = 0; kk < 4; kk++) {
                    wmma::fragment<wmma::matrix_a, 16, 16, 8, wmma::precision::tf32, wmma::row_major> a0, a1;
                    wmma::load_matrix_sync(a0, As + (mrow * 32) * 36 + kk * 8, 36);
                    wmma::load_matrix_sync(a1, As + (mrow * 32 + 16) * 36 + kk * 8, 36);
                    wmma::fragment<wmma::matrix_b, 16, 16, 8, wmma::precision::tf32, wmma::row_major> bf;
                    wmma::load_matrix_sync(bf, Bs + (kk * 8) * 68 + ncol * 16, 68);
                    wmma::mma_sync(acc0, a0, bf, acc0);
                    wmma::mma_sync(acc1, a1, bf, acc1);
                }
                __syncthreads();
            }
#undef S1_ISSUE

            wmma::store_matrix_sync(
                g_gates + (size_t)gate * TBH + (size_t)(m0 + mrow * 32) * 1024 + col0s + ncol * 16,
                acc0, 1024, wmma::mem_row_major);
            wmma::store_matrix_sync(
                g_gates + (size_t)gate * TBH + (size_t)(m0 + mrow * 32 + 16) * 1024 + col0s + ncol * 16,
                acc1, 1024, wmma::mem_row_major);

            __syncthreads();
            if (tid == 0) red_rel_add(&g_mt_cnt[mtile]);
        }
        return;
    }

    // ==================== RECURRENCE ====================
    const int kgrp  = wid >> 1;          // 0..7, K range [kgrp*128, +128)
    const int mpair = wid & 1;           // rows [32*mpair, +32)
    const int ptid  = tid & 63;          // id within pair
    const int col0  = cta << 4;
    float* kbase = sm + kgrp * 6336;     // this pair's region
    float* sbias = sm + 50688;           // [4][16]

    __shared__ unsigned s_gen0;
    if (tid == 0) s_gen0 = *(volatile unsigned*)&g_bar_gen;
    if (tid < 64) {                      // [br_tot, bz_tot, b_in, b_hn][16]
        int a = tid >> 4, i = tid & 15, jc = col0 + i;
        float v = (a == 0) ? (b_ir[jc] + b_hr[jc])
                : (a == 1) ? (b_iz[jc] + b_hz[jc])
                : (a == 2) ? b_in[jc] : b_hn[jc];
        sbias[a * 16 + i] = v;
    }
    const unsigned s1base = *(volatile unsigned*)&g_mt_cnt[255];
    __syncthreads();
    const unsigned gen0 = s_gen0;

    // pointwise ownership: col jcol, rows r2, r2+1
    const int c_pb = tid & 15;
    const int r2   = (tid >> 4) << 1;
    const int jcol = col0 + c_pb;

    float pg_r[2], pg_z[2], pg_n[2];
    float hpq[2] = {0.f, 0.f};

    if (tid == 1) {
        while ((int)(ld_acq(&g_mt_cnt[0]) - (s1base + 48u)) < 0) { }
    }
    __syncthreads();
#pragma unroll
    for (int q = 0; q < 2; q++) {
        size_t gi = (size_t)(r2 + q) * 1024 + jcol;
        pg_r[q] = g_gates[gi];
        pg_z[q] = g_gates[TBH + gi];
        pg_n[q] = g_gates[2ull * TBH + gi];
    }

    for (int t = 0; t < TSZ; t++) {
        if (t > 0) {
            // ===== Phase A: per-kgrp independent K pipeline =====
            const float* hsrc = g_ht[(t - 1) & 1];

            wmma::fragment<wmma::accumulator, 16, 16, 8, float> acc[2][3];
#pragma unroll
            for (int mi = 0; mi < 2; mi++)
#pragma unroll
                for (int g = 0; g < 3; g++) wmma::fill_fragment(acc[mi][g], 0.0f);

            // issue chunk c (16 k-cols of this kgrp's K range) into stage c%3
#define K_ISSUE(c)                                                              \
            {                                                                   \
                float* As = kbase + ((c) % 3) * 2112;                           \
                float* Bs = As + 1280;                                          \
                const int kofs = kgrp * 128 + (c) * 16;                         \
                _Pragma("unroll")                                               \
                for (int q = 0; q < 4; q++) {                                   \
                    int o = ptid + q * 64;                                      \
                    int row = o >> 2, c4 = (o & 3) << 2;                        \
                    cp16(As + row * 20 + c4,                                    \
                         hsrc + (size_t)row * 1024 + kofs + c4);                \
                }                                                               \
                _Pragma("unroll")                                               \
                for (int q = 0; q < 3; q++) {                                   \
                    int o = ptid + q * 64;                                      \
                    int row = o / 12, cw = (o % 12) << 2;                       \
                    int gate = cw >> 4;                                         \
                    cp16(Bs + row * 52 + cw,                                    \
                         g_Wall + (size_t)gate * 1048576                        \
                                + (size_t)(kofs + row) * 1024                   \
                                + col0 + (cw & 15));                            \
                }                                                               \
                CP_COMMIT();                                                    \
            }

            K_ISSUE(0);
            K_ISSUE(1);

#pragma unroll
            for (int it = 0; it < 8; it++) {
                if (it < 7) CP_WAIT1(); else CP_WAIT0();
                PAIR_BAR(1 + kgrp);                 // both warps done consuming it-1
                if (it < 6) K_ISSUE(it + 2);

                const float* A = kbase + (it % 3) * 2112 + (mpair * 32) * 20;
                const float* B = kbase + (it % 3) * 2112 + 1280;
#pragma unroll
                for (int kk = 0; kk < 2; kk++) {
                    wmma::fragment<wmma::matrix_a, 16, 16, 8, wmma::precision::tf32, wmma::row_major> a0, a1;
                    wmma::load_matrix_sync(a0, A + kk * 8, 20);
                    wmma::load_matrix_sync(a1, A + 16 * 20 + kk * 8, 20);
#pragma unroll
                    for (int g = 0; g < 3; g++) {
                        wmma::fragment<wmma::matrix_b, 16, 16, 8, wmma::precision::tf32, wmma::row_major> bf;
                        wmma::load_matrix_sync(bf, B + (kk * 8) * 52 + g * 16, 52);
                        wmma::mma_sync(acc[0][g], a0, bf, acc[0][g]);
                        wmma::mma_sync(acc[1][g], a1, bf, acc[1][g]);
                    }
                }
            }
#undef K_ISSUE

            // partial store into own region (stage 0 alias; consumed at it=6)
            PAIR_BAR(1 + kgrp);
#pragma unroll
            for (int mi = 0; mi < 2; mi++)
#pragma unroll
                for (int g = 0; g < 3; g++)
                    wmma::store_matrix_sync(kbase + (mpair * 32 + mi * 16) * 48 + g * 16,
                                            acc[mi][g], 48, wmma::mem_row_major);
            __syncthreads();   // all partials visible to all threads
        }

        // ===== fused 8-way reduce + pointwise (all 512 threads, 2 outputs) =====
        {
            const size_t toff = (size_t)t * BH;
#pragma unroll
            for (int q = 0; q < 2; q++) {
                int row = r2 + q;
                float sr = 0.f, sz = 0.f, sn = 0.f;
                if (t > 0) {
#pragma unroll
                    for (int kg = 0; kg < 8; kg++) {
                        const float* p = sm + kg * 6336 + row * 48;
                        sr += p[c_pb];
                        sz += p[16 + c_pb];
                        sn += p[32 + c_pb];
                    }
                }
                float gr = pg_r[q] + sbias[c_pb] + sr;
                float gz = pg_z[q] + sbias[16 + c_pb] + sz;
                float gn = pg_n[q] + sbias[32 + c_pb];
                float hn = sbias[48 + c_pb] + sn;
                float r = 1.0f / (1.0f + expf(-gr));
                float z = 1.0f / (1.0f + expf(-gz));
                float n = tanhf(gn + r * hn);
                float hnew = (1.0f - z) * n + z * hpq[q];
                hpq[q] = hnew;
                out[toff + (size_t)row * 1024 + jcol] = hnew;
                g_ht[t & 1][(size_t)row * 1024 + jcol] = wmma::__float_to_tf32(hnew);
                if (t == TSZ - 1 && write_hfinal)
                    out[TBH + (size_t)row * 1024 + jcol] = hnew;
            }
        }

        if (t == TSZ - 1) break;

        // ===== split grid barrier + stage1 poll + gate prefetch =====
        __syncthreads();
        const unsigned target = gen0 + (unsigned)t + 1u;
        bool released = false;
        if (tid == 0) {
            unsigned old;
            asm volatile("atom.acq_rel.gpu.add.u32 %0, [%1], %2;"
                         : "=r"(old) : "l"(&g_bar_cnt), "r"(1u) : "memory");
            if (old == NREC - 1u) {
                asm volatile("st.relaxed.gpu.u32 [%0], %1;" :: "l"(&g_bar_cnt), "r"(0u) : "memory");
                st_rel(&g_bar_gen, target);
                released = true;
            }
        }
        if (tid == 1) {                      // gates for t+1 produced?
            int mt = (t + 1) >> 1;
            while ((int)(ld_acq(&g_mt_cnt[mt]) - (s1base + 48u)) < 0) { }
        }
        __syncthreads();
        {
            const size_t toff1 = (size_t)(t + 1) * BH;
#pragma unroll
            for (int q = 0; q < 2; q++) {
                size_t gi = toff1 + (size_t)(r2 + q) * 1024 + jcol;
                pg_r[q] = g_gates[gi];
                pg_z[q] = g_gates[TBH + gi];
                pg_n[q] = g_gates[2ull * TBH + gi];
            }
        }
        if (tid == 0 && !released) {
            unsigned v;
            do {
                asm volatile("ld.acquire.gpu.u32 %0, [%1];" : "=r"(v) : "l"(&g_bar_gen) : "memory");
            } while ((int)(v - target) < 0);
        }
        __syncthreads();
    }
}

// ---------------------------------------------------------------------------
extern "C" void kernel_launch(void* const* d_in, const int* in_sizes, int n_in,
                              void* d_out, int out_size) {
    const float* x    = (const float*)d_in[0];
    const float* W_ir = (const float*)d_in[1];
    const float* b_ir = (const float*)d_in[2];
    const float* W_hr = (const float*)d_in[3];
    const float* b_hr = (const float*)d_in[4];
    const float* W_iz = (const float*)d_in[5];
    const float* b_iz = (const float*)d_in[6];
    const float* W_hz = (const float*)d_in[7];
    const float* b_hz = (const float*)d_in[8];
    const float* W_in = (const float*)d_in[9];
    const float* b_in = (const float*)d_in[10];
    const float* W_hn = (const float*)d_in[11];
    const float* b_hn = (const float*)d_in[12];
    float* out = (float*)d_out;

    const int has_hfinal = ((size_t)out_size >= TBH + (size_t)BH) ? 1 : 0;

    static bool init_done = false;
    if (!init_done) {
        cudaFuncSetAttribute(fused_kernel,
                             cudaFuncAttributeMaxDynamicSharedMemorySize, FUSED_SMEM);
        init_done = true;
    }

    prep_kernel<<<38912, 256>>>(x, W_hr, W_hz, W_hn, W_ir, W_iz, W_in);
    fused_kernel<<<NTOT, NTHR, FUSED_SMEM>>>(b_ir, b_hr, b_iz, b_hz, b_in, b_hn,
                                             out, has_hfinal);
}

// round 14
// speedup vs baseline: 1.0288x; 1.0288x over previous
#include <cuda_runtime.h>
#include <mma.h>
#include <math.h>
#include <stdint.h>

using namespace nvcuda;

#define TSZ   512
#define INSZ  1024
#define HIDSZ 1024
#define BH    65536                        // 64*1024
static constexpr size_t TBH = 33554432ull; // 512*64*1024

#define NREC  64                           // recurrence CTAs
#define NS1   80                           // stage1 worker CTAs
#define NTOT  144
#define NTHR  512

// Device-global scratch (no allocations allowed)
__device__ float g_gates[3ull * TBH];           // [gate][t*64+b][hid]
__device__ float g_Wall[6ull * 1048576];        // tf32 W: [hr|hz|hn|ir|iz|in]
__device__ float g_xt[32768ull * 1024];         // tf32 x, time-major [t*64+b][k]
__device__ float g_ht[2][BH];                   // tf32 h ping-pong
__device__ unsigned g_leaf_cnt[8 * 32];         // tree barrier: 8 leaves, 128B apart
__device__ unsigned g_leaf_gen[8 * 32];
__device__ unsigned g_root_cnt = 0;
__device__ unsigned g_root_gen = 0;
__device__ unsigned g_mt_cnt[256];              // stage1 per-mtile counters (monotonic)

// ---------------------------------------------------------------------------
__device__ __forceinline__ unsigned ld_acq(const unsigned* p) {
    unsigned v;
    asm volatile("ld.acquire.gpu.u32 %0, [%1];" : "=r"(v) : "l"(p) : "memory");
    return v;
}
__device__ __forceinline__ void st_rel(unsigned* p, unsigned v) {
    asm volatile("st.release.gpu.u32 [%0], %1;" :: "l"(p), "r"(v) : "memory");
}
__device__ __forceinline__ unsigned atom_add_acqrel(unsigned* p) {
    unsigned old;
    asm volatile("atom.acq_rel.gpu.add.u32 %0, [%1], %2;"
                 : "=r"(old) : "l"(p), "r"(1u) : "memory");
    return old;
}
__device__ __forceinline__ void red_rel_add(unsigned* p) {
    asm volatile("red.release.gpu.global.add.u32 [%0], %1;" :: "l"(p), "r"(1u) : "memory");
}
__device__ __forceinline__ void cp16(void* sdst, const void* gsrc) {
    unsigned s;
    asm("{ .reg .u64 t; cvta.to.shared.u64 t, %1; cvt.u32.u64 %0, t; }" : "=r"(s) : "l"(sdst));
    asm volatile("cp.async.cg.shared.global [%0], [%1], 16;" :: "r"(s), "l"(gsrc));
}
#define CP_COMMIT() asm volatile("cp.async.commit_group;")
#define CP_WAIT0()  asm volatile("cp.async.wait_group 0;")

// ---------------------------------------------------------------------------
// Prep: tf32 weights -> g_Wall[0..5] (hr,hz,hn,ir,iz,in); x tf32 + transpose.
// ---------------------------------------------------------------------------
__global__ void prep_kernel(const float* __restrict__ x,
                            const float* __restrict__ Whr, const float* __restrict__ Whz,
                            const float* __restrict__ Whn, const float* __restrict__ Wir,
                            const float* __restrict__ Wiz, const float* __restrict__ Win) {
    const int bid = blockIdx.x, tid = threadIdx.x;
    if (bid < 6144) {
        int which = bid >> 10;
        int o = (bid & 1023) * 256 + tid;
        const float* src = (which == 0) ? Whr : (which == 1) ? Whz : (which == 2) ? Whn
                         : (which == 3) ? Wir : (which == 4) ? Wiz : Win;
        float4 v = ((const float4*)src)[o];
        v.x = wmma::__float_to_tf32(v.x); v.y = wmma::__float_to_tf32(v.y);
        v.z = wmma::__float_to_tf32(v.z); v.w = wmma::__float_to_tf32(v.w);
        ((float4*)(g_Wall + (size_t)which * 1048576))[o] = v;
    } else {
        int m = bid - 6144;                     // 0..32767, m = t*64+b
        int t = m >> 6, b = m & 63;
        float4 v = ((const float4*)(x + ((size_t)b * TSZ + t) * INSZ))[tid];
        v.x = wmma::__float_to_tf32(v.x); v.y = wmma::__float_to_tf32(v.y);
        v.z = wmma::__float_to_tf32(v.z); v.w = wmma::__float_to_tf32(v.w);
        ((float4*)(g_xt + (size_t)m * 1024))[tid] = v;
    }
}

// ---------------------------------------------------------------------------
// Fused persistent kernel, grid 144 x 512 (R11 structure).
//   CTAs [0,64):  recurrence, owner-computes cols [16c,16c+16) of all 3 gates.
//                 16 warps = 8 kgrp(K=128) x 2 mpair(32 rows). Double-buffered
//                 cp.async K-loop with full-CTA syncs (R11). NEW: tree barrier
//                 + distributed 8-way reduce fused into pointwise.
//   CTAs [64,144): stage1 workers (R11, unchanged).
// Recurrence smem (floats; strides 16B-aligned):
//   hb  @0      : 2 stages x 8 kgrp x [64][20]   (20480 fl)
//   Wb  @20480  : 2 stages x 8 kgrp x [16][52]   (13312 fl)
//   red alias @0: 8 x [64][56]                    (28672 fl, post-K-loop)
//   bias@33792  : [4][16]
// Total 33856 fl = 135424 B. Stage1 path uses sm[0..13568).
// ---------------------------------------------------------------------------
#define FUSED_SMEM 135424

__global__ __launch_bounds__(NTHR, 1)
void fused_kernel(const float* __restrict__ b_ir, const float* __restrict__ b_hr,
                  const float* __restrict__ b_iz, const float* __restrict__ b_hz,
                  const float* __restrict__ b_in, const float* __restrict__ b_hn,
                  float* __restrict__ out, int write_hfinal) {
    extern __shared__ __align__(16) float sm[];
    const int cta = blockIdx.x;
    const int tid = threadIdx.x;
    const int wid = tid >> 5;

    if (cta >= NREC) {
        // ==================== STAGE1 WORKER (R11) ====================
        const int worker = cta - NREC;
        const int mrow = wid & 3;
        const int ncol = wid >> 2;

        for (int u = worker; u < 12288; u += NS1) {
            const int mtile = u / 48;
            const int sub   = u - mtile * 48;
            const int gate  = sub >> 4;
            const int col0s = (sub & 15) << 6;
            const int m0    = mtile << 7;
            const float* Wp = g_Wall + (size_t)(3 + gate) * 1048576;

            wmma::fragment<wmma::accumulator, 16, 16, 8, float> acc0, acc1;
            wmma::fill_fragment(acc0, 0.0f);
            wmma::fill_fragment(acc1, 0.0f);

#define S1_ISSUE(c)                                                             \
            {                                                                   \
                float* As = sm + ((c) & 1) * 6784;                              \
                float* Bs = As + 4608;                                          \
                _Pragma("unroll")                                               \
                for (int q = 0; q < 2; q++) {                                   \
                    int o = tid + q * 512;                                      \
                    int row = o >> 3, c4 = (o & 7) << 2;                        \
                    cp16(As + row * 36 + c4,                                    \
                         g_xt + (size_t)(m0 + row) * 1024 + (c) * 32 + c4);     \
                }                                                               \
                {                                                               \
                    int row = tid >> 4, c4 = (tid & 15) << 2;                   \
                    cp16(Bs + row * 68 + c4,                                    \
                         Wp + (size_t)((c) * 32 + row) * 1024 + col0s + c4);    \
                }                                                               \
            }

            S1_ISSUE(0); CP_COMMIT();
            for (int c = 0; c < 32; c++) {
                CP_WAIT0();
                __syncthreads();
                if (c < 31) { S1_ISSUE(c + 1); CP_COMMIT(); }

                const float* As = sm + (c & 1) * 6784;
                const float* Bs = As + 4608;
#pragma unroll
                for (int kk = 0; kk < 4; kk++) {
                    wmma::fragment<wmma::matrix_a, 16, 16, 8, wmma::precision::tf32, wmma::row_major> a0, a1;
                    wmma::load_matrix_sync(a0, As + (mrow * 32) * 36 + kk * 8, 36);
                    wmma::load_matrix_sync(a1, As + (mrow * 32 + 16) * 36 + kk * 8, 36);
                    wmma::fragment<wmma::matrix_b, 16, 16, 8, wmma::precision::tf32, wmma::row_major> bf;
                    wmma::load_matrix_sync(bf, Bs + (kk * 8) * 68 + ncol * 16, 68);
                    wmma::mma_sync(acc0, a0, bf, acc0);
                    wmma::mma_sync(acc1, a1, bf, acc1);
                }
                __syncthreads();
            }
#undef S1_ISSUE

            wmma::store_matrix_sync(
                g_gates + (size_t)gate * TBH + (size_t)(m0 + mrow * 32) * 1024 + col0s + ncol * 16,
                acc0, 1024, wmma::mem_row_major);
            wmma::store_matrix_sync(
                g_gates + (size_t)gate * TBH + (size_t)(m0 + mrow * 32 + 16) * 1024 + col0s + ncol * 16,
                acc1, 1024, wmma::mem_row_major);

            __syncthreads();
            if (tid == 0) red_rel_add(&g_mt_cnt[mtile]);
        }
        return;
    }

    // ==================== RECURRENCE ====================
    float* hb    = sm;                 // 2*8*[64][20]
    float* Wb    = sm + 20480;         // 2*8*[16][52]
    float* red   = sm;                 // 8*[64][56] alias (post-K-loop)
    float* sbias = sm + 33792;         // [4][16]

    const int kgrp  = wid >> 1;          // 0..7, K range [kgrp*128, +128)
    const int mpair = wid & 1;           // rows [32*mpair, +32)
    const int col0  = cta << 4;
    const int g8    = cta >> 3;          // barrier leaf group

    __shared__ unsigned s_gen0;
    if (tid == 0) s_gen0 = *(volatile unsigned*)&g_root_gen;
    if (tid < 64) {                      // [br_tot, bz_tot, b_in, b_hn][16]
        int a = tid >> 4, i = tid & 15, jc = col0 + i;
        float v = (a == 0) ? (b_ir[jc] + b_hr[jc])
                : (a == 1) ? (b_iz[jc] + b_hz[jc])
                : (a == 2) ? b_in[jc] : b_hn[jc];
        sbias[a * 16 + i] = v;
    }
    const unsigned s1base = *(volatile unsigned*)&g_mt_cnt[255];
    __syncthreads();
    const unsigned gen0 = s_gen0;

    // pointwise ownership: col jcol, rows r2, r2+1
    const int c_pb = tid & 15;
    const int r2   = (tid >> 4) << 1;
    const int jcol = col0 + c_pb;

    float pg_r[2], pg_z[2], pg_n[2];
    float hpq[2] = {0.f, 0.f};

    if (tid == 1) {
        while ((int)(ld_acq(&g_mt_cnt[0]) - (s1base + 48u)) < 0) { }
    }
    __syncthreads();
#pragma unroll
    for (int q = 0; q < 2; q++) {
        size_t gi = (size_t)(r2 + q) * 1024 + jcol;
        pg_r[q] = g_gates[gi];
        pg_z[q] = g_gates[TBH + gi];
        pg_n[q] = g_gates[2ull * TBH + gi];
    }

    for (int t = 0; t < TSZ; t++) {
        if (t > 0) {
            // ===== Phase A (R11): double-buffered K-loop, full-CTA syncs =====
            const float* hsrc = g_ht[(t - 1) & 1];

            wmma::fragment<wmma::accumulator, 16, 16, 8, float> acc[2][3];
#pragma unroll
            for (int mi = 0; mi < 2; mi++)
#pragma unroll
                for (int g = 0; g < 3; g++) wmma::fill_fragment(acc[mi][g], 0.0f);

#define R_ISSUE(c)                                                              \
            {                                                                   \
                int kofs = (c) * 16;                                            \
                _Pragma("unroll")                                               \
                for (int q = 0; q < 4; q++) {                                   \
                    int o = tid + q * 512;                                      \
                    int kg = o >> 8, idx = o & 255;                             \
                    int row = idx >> 2, c4 = (idx & 3) << 2;                    \
                    cp16(hb + (((c) & 1) * 8 + kg) * 1280 + row * 20 + c4,      \
                         hsrc + (size_t)row * 1024 + kg * 128 + kofs + c4);     \
                }                                                               \
                _Pragma("unroll")                                               \
                for (int q = 0; q < 3; q++) {                                   \
                    int o = tid + q * 512;                                      \
                    int kg = o / 192, idx = o % 192;                            \
                    int row = idx / 12, cw = (idx % 12) << 2;                   \
                    int gate = cw >> 4;                                         \
                    cp16(Wb + (((c) & 1) * 8 + kg) * 832 + row * 52 + cw,       \
                         g_Wall + (size_t)gate * 1048576                        \
                                + (size_t)(kg * 128 + kofs + row) * 1024        \
                                + col0 + (cw & 15));                            \
                }                                                               \
            }

            R_ISSUE(0); CP_COMMIT();

            for (int it = 0; it < 8; it++) {
                CP_WAIT0();
                __syncthreads();
                if (it < 7) { R_ISSUE(it + 1); CP_COMMIT(); }

                const float* A = hb + ((it & 1) * 8 + kgrp) * 1280 + (mpair * 32) * 20;
                const float* B = Wb + ((it & 1) * 8 + kgrp) * 832;
#pragma unroll
                for (int kk = 0; kk < 2; kk++) {
                    wmma::fragment<wmma::matrix_a, 16, 16, 8, wmma::precision::tf32, wmma::row_major> a0, a1;
                    wmma::load_matrix_sync(a0, A + kk * 8, 20);
                    wmma::load_matrix_sync(a1, A + 16 * 20 + kk * 8, 20);
#pragma unroll
                    for (int g = 0; g < 3; g++) {
                        wmma::fragment<wmma::matrix_b, 16, 16, 8, wmma::precision::tf32, wmma::row_major> bf;
                        wmma::load_matrix_sync(bf, B + (kk * 8) * 52 + g * 16, 52);
                        wmma::mma_sync(acc[0][g], a0, bf, acc[0][g]);
                        wmma::mma_sync(acc[1][g], a1, bf, acc[1][g]);
                    }
                }
                __syncthreads();
            }
#undef R_ISSUE

            // ===== NEW: all 8 kgrps store partials (stride 56); one sync =====
            {
                float* myred = red + kgrp * 3584;
#pragma unroll
                for (int mi = 0; mi < 2; mi++)
#pragma unroll
                    for (int g = 0; g < 3; g++)
                        wmma::store_matrix_sync(myred + (mpair * 32 + mi * 16) * 56 + g * 16,
                                                acc[mi][g], 56, wmma::mem_row_major);
            }
            __syncthreads();
        }

        // ===== pointwise with inline 8-way reduction =====
        {
            const size_t toff = (size_t)t * BH;
#pragma unroll
            for (int q = 0; q < 2; q++) {
                int row = r2 + q;
                float sr = 0.f, sz = 0.f, sn = 0.f;
                if (t > 0) {
#pragma unroll
                    for (int kg = 0; kg < 8; kg++) {
                        const float* p = red + kg * 3584 + row * 56;
                        sr += p[c_pb];
                        sz += p[16 + c_pb];
                        sn += p[32 + c_pb];
                    }
                }
                float gr = pg_r[q] + sbias[c_pb] + sr;
                float gz = pg_z[q] + sbias[16 + c_pb] + sz;
                float gn = pg_n[q] + sbias[32 + c_pb];
                float hn = sbias[48 + c_pb] + sn;
                float r = 1.0f / (1.0f + expf(-gr));
                float z = 1.0f / (1.0f + expf(-gz));
                float n = tanhf(gn + r * hn);
                float hnew = (1.0f - z) * n + z * hpq[q];
                hpq[q] = hnew;
                out[toff + (size_t)row * 1024 + jcol] = hnew;
                g_ht[t & 1][(size_t)row * 1024 + jcol] = wmma::__float_to_tf32(hnew);
                if (t == TSZ - 1 && write_hfinal)
                    out[TBH + (size_t)row * 1024 + jcol] = hnew;
            }
        }

        if (t == TSZ - 1) break;

        // ===== tree barrier (8x8) + stage1 poll + gate prefetch =====
        __syncthreads();
        const unsigned target = gen0 + (unsigned)t + 1u;
        bool finisher = false;
        if (tid == 0) {
            unsigned old = atom_add_acqrel(&g_leaf_cnt[g8 * 32]);
            if ((old & 7u) == 7u) {                     // last of my leaf
                finisher = true;
                unsigned r = atom_add_acqrel(&g_root_cnt);
                if ((r & 7u) == 7u)                     // last leaf overall
                    st_rel(&g_root_gen, target);
            }
        }
        if (tid == 1) {                                  // gates for t+1 produced?
            int mt = (t + 1) >> 1;
            while ((int)(ld_acq(&g_mt_cnt[mt]) - (s1base + 48u)) < 0) { }
        }
        __syncthreads();
        {   // gate prefetch overlaps barrier propagation
            const size_t toff1 = (size_t)(t + 1) * BH;
#pragma unroll
            for (int q = 0; q < 2; q++) {
                size_t gi = toff1 + (size_t)(r2 + q) * 1024 + jcol;
                pg_r[q] = g_gates[gi];
                pg_z[q] = g_gates[TBH + gi];
                pg_n[q] = g_gates[2ull * TBH + gi];
            }
        }
        if (tid == 0) {
            if (finisher) {                              // propagate root -> leaf
                while ((int)(ld_acq(&g_root_gen) - target) < 0) { }
                st_rel(&g_leaf_gen[g8 * 32], target);
            } else {
                while ((int)(ld_acq(&g_leaf_gen[g8 * 32]) - target) < 0) { }
            }
        }
        __syncthreads();
    }
}

// ---------------------------------------------------------------------------
extern "C" void kernel_launch(void* const* d_in, const int* in_sizes, int n_in,
                              void* d_out, int out_size) {
    const float* x    = (const float*)d_in[0];
    const float* W_ir = (const float*)d_in[1];
    const float* b_ir = (const float*)d_in[2];
    const float* W_hr = (const float*)d_in[3];
    const float* b_hr = (const float*)d_in[4];
    const float* W_iz = (const float*)d_in[5];
    const float* b_iz = (const float*)d_in[6];
    const float* W_hz = (const float*)d_in[7];
    const float* b_hz = (const float*)d_in[8];
    const float* W_in = (const float*)d_in[9];
    const float* b_in = (const float*)d_in[10];
    const float* W_hn = (const float*)d_in[11];
    const float* b_hn = (const float*)d_in[12];
    float* out = (float*)d_out;

    const int has_hfinal = ((size_t)out_size >= TBH + (size_t)BH) ? 1 : 0;

    static bool init_done = false;
    if (!init_done) {
        cudaFuncSetAttribute(fused_kernel,
                             cudaFuncAttributeMaxDynamicSharedMemorySize, FUSED_SMEM);
        init_done = true;
    }

    prep_kernel<<<38912, 256>>>(x, W_hr, W_hz, W_hn, W_ir, W_iz, W_in);
    fused_kernel<<<NTOT, NTHR, FUSED_SMEM>>>(b_ir, b_hr, b_iz, b_hz, b_in, b_hn,
                                             out, has_hfinal);
}

// round 16
// speedup vs baseline: 1.5517x; 1.5082x over previous
#include <cuda_runtime.h>
#include <mma.h>
#include <math.h>
#include <stdint.h>

using namespace nvcuda;

#define TSZ   512
#define INSZ  1024
#define HIDSZ 1024
#define BH    65536                        // 64*1024
static constexpr size_t TBH = 33554432ull; // 512*64*1024

#define NREC  64                           // recurrence CTAs
#define NS1   80                           // stage1 worker CTAs
#define NTOT  144
#define NTHR  512

// Device-global scratch (no allocations allowed)
__device__ float g_gates[3ull * TBH];           // [gate][t*64+b][hid]
__device__ float g_Wall[6ull * 1048576];        // tf32 W: [hr|hz|hn|ir|iz|in]
__device__ float g_xt[32768ull * 1024];         // tf32 x, time-major [t*64+b][k]
__device__ float g_ht[2][BH];                   // tf32 h ping-pong
__device__ unsigned g_bar_cnt = 0;              // grid barrier (recur CTAs only)
__device__ unsigned g_bar_gen = 0;
__device__ unsigned g_mt_cnt[256];              // stage1 per-mtile counters (monotonic)

// ---------------------------------------------------------------------------
__device__ __forceinline__ unsigned ld_acq(const unsigned* p) {
    unsigned v;
    asm volatile("ld.acquire.gpu.u32 %0, [%1];" : "=r"(v) : "l"(p) : "memory");
    return v;
}
__device__ __forceinline__ void st_rel(unsigned* p, unsigned v) {
    asm volatile("st.release.gpu.u32 [%0], %1;" :: "l"(p), "r"(v) : "memory");
}
__device__ __forceinline__ void red_rel_add(unsigned* p) {
    asm volatile("red.release.gpu.global.add.u32 [%0], %1;" :: "l"(p), "r"(1u) : "memory");
}
__device__ __forceinline__ void cp16(void* sdst, const void* gsrc) {
    unsigned s;
    asm("{ .reg .u64 t; cvta.to.shared.u64 t, %1; cvt.u32.u64 %0, t; }" : "=r"(s) : "l"(sdst));
    asm volatile("cp.async.cg.shared.global [%0], [%1], 16;" :: "r"(s), "l"(gsrc));
}
#define CP_COMMIT() asm volatile("cp.async.commit_group;")
#define CP_WAIT0()  asm volatile("cp.async.wait_group 0;")

// ---------------------------------------------------------------------------
// Prep: tf32 weights -> g_Wall[0..5] (hr,hz,hn,ir,iz,in); x tf32 + transpose.
// ---------------------------------------------------------------------------
__global__ void prep_kernel(const float* __restrict__ x,
                            const float* __restrict__ Whr, const float* __restrict__ Whz,
                            const float* __restrict__ Whn, const float* __restrict__ Wir,
                            const float* __restrict__ Wiz, const float* __restrict__ Win) {
    const int bid = blockIdx.x, tid = threadIdx.x;
    if (bid < 6144) {
        int which = bid >> 10;
        int o = (bid & 1023) * 256 + tid;
        const float* src = (which == 0) ? Whr : (which == 1) ? Whz : (which == 2) ? Whn
                         : (which == 3) ? Wir : (which == 4) ? Wiz : Win;
        float4 v = ((const float4*)src)[o];
        v.x = wmma::__float_to_tf32(v.x); v.y = wmma::__float_to_tf32(v.y);
        v.z = wmma::__float_to_tf32(v.z); v.w = wmma::__float_to_tf32(v.w);
        ((float4*)(g_Wall + (size_t)which * 1048576))[o] = v;
    } else {
        int m = bid - 6144;                     // 0..32767, m = t*64+b
        int t = m >> 6, b = m & 63;
        float4 v = ((const float4*)(x + ((size_t)b * TSZ + t) * INSZ))[tid];
        v.x = wmma::__float_to_tf32(v.x); v.y = wmma::__float_to_tf32(v.y);
        v.z = wmma::__float_to_tf32(v.z); v.w = wmma::__float_to_tf32(v.w);
        ((float4*)(g_xt + (size_t)m * 1024))[tid] = v;
    }
}

// ---------------------------------------------------------------------------
// Fused persistent kernel, grid 144 x 512 — R11 champion structure; ONLY
// change: single __syncthreads per K-iteration (trailing sync removed; the
// leading wait+sync of it+1 already orders compute(it) before issue(it+2)).
// ---------------------------------------------------------------------------
#define FUSED_SMEM 221440

__global__ __launch_bounds__(NTHR, 1)
void fused_kernel(const float* __restrict__ b_ir, const float* __restrict__ b_hr,
                  const float* __restrict__ b_iz, const float* __restrict__ b_hz,
                  const float* __restrict__ b_in, const float* __restrict__ b_hn,
                  float* __restrict__ out, int write_hfinal) {
    extern __shared__ __align__(16) float sm[];
    const int cta = blockIdx.x;
    const int tid = threadIdx.x;
    const int wid = tid >> 5;

    if (cta >= NREC) {
        // ==================== STAGE1 WORKER ====================
        const int worker = cta - NREC;
        const int mrow = wid & 3;
        const int ncol = wid >> 2;

        for (int u = worker; u < 12288; u += NS1) {
            const int mtile = u / 48;
            const int sub   = u - mtile * 48;
            const int gate  = sub >> 4;
            const int col0s = (sub & 15) << 6;
            const int m0    = mtile << 7;
            const float* Wp = g_Wall + (size_t)(3 + gate) * 1048576;

            wmma::fragment<wmma::accumulator, 16, 16, 8, float> acc0, acc1;
            wmma::fill_fragment(acc0, 0.0f);
            wmma::fill_fragment(acc1, 0.0f);

#define S1_ISSUE(c)                                                             \
            {                                                                   \
                float* As = sm + ((c) & 1) * 6784;                              \
                float* Bs = As + 4608;                                          \
                _Pragma("unroll")                                               \
                for (int q = 0; q < 2; q++) {                                   \
                    int o = tid + q * 512;                                      \
                    int row = o >> 3, c4 = (o & 7) << 2;                        \
                    cp16(As + row * 36 + c4,                                    \
                         g_xt + (size_t)(m0 + row) * 1024 + (c) * 32 + c4);     \
                }                                                               \
                {                                                               \
                    int row = tid >> 4, c4 = (tid & 15) << 2;                   \
                    cp16(Bs + row * 68 + c4,                                    \
                         Wp + (size_t)((c) * 32 + row) * 1024 + col0s + c4);    \
                }                                                               \
            }

            S1_ISSUE(0); CP_COMMIT();
            for (int c = 0; c < 32; c++) {
                CP_WAIT0();
                __syncthreads();               // single sync per iteration
                if (c < 31) { S1_ISSUE(c + 1); CP_COMMIT(); }

                const float* As = sm + (c & 1) * 6784;
                const float* Bs = As + 4608;
#pragma unroll
                for (int kk = 0; kk < 4; kk++) {
                    wmma::fragment<wmma::matrix_a, 16, 16, 8, wmma::precision::tf32, wmma::row_major> a0, a1;
                    wmma::load_matrix_sync(a0, As + (mrow * 32) * 36 + kk * 8, 36);
                    wmma::load_matrix_sync(a1, As + (mrow * 32 + 16) * 36 + kk * 8, 36);
                    wmma::fragment<wmma::matrix_b, 16, 16, 8, wmma::precision::tf32, wmma::row_major> bf;
                    wmma::load_matrix_sync(bf, Bs + (kk * 8) * 68 + ncol * 16, 68);
                    wmma::mma_sync(acc0, a0, bf, acc0);
                    wmma::mma_sync(acc1, a1, bf, acc1);
                }
            }
#undef S1_ISSUE

            wmma::store_matrix_sync(
                g_gates + (size_t)gate * TBH + (size_t)(m0 + mrow * 32) * 1024 + col0s + ncol * 16,
                acc0, 1024, wmma::mem_row_major);
            wmma::store_matrix_sync(
                g_gates + (size_t)gate * TBH + (size_t)(m0 + mrow * 32 + 16) * 1024 + col0s + ncol * 16,
                acc1, 1024, wmma::mem_row_major);

            __syncthreads();
            if (tid == 0) red_rel_add(&g_mt_cnt[mtile]);
        }
        return;
    }

    // ==================== RECURRENCE ====================
    float* hb    = sm;                 // 2*8*[64][20]; 'pre' aliases sm[0..3072)
    float* Wb    = sm + 20480;         // 2*8*[16][52]
    float* red   = sm + 33792;         // 7*[64][48]
    float* sbias = sm + 55296;         // [4][16]
    float* pre   = sm;

    const int kgrp  = wid >> 1;          // 0..7, K range [kgrp*128, +128)
    const int mpair = wid & 1;           // rows [32*mpair, +32)
    const int col0  = cta << 4;

    __shared__ unsigned s_gen0;
    if (tid == 0) s_gen0 = *(volatile unsigned*)&g_bar_gen;
    if (tid < 64) {                      // [br_tot, bz_tot, b_in, b_hn][16]
        int a = tid >> 4, i = tid & 15, jc = col0 + i;
        float v = (a == 0) ? (b_ir[jc] + b_hr[jc])
                : (a == 1) ? (b_iz[jc] + b_hz[jc])
                : (a == 2) ? b_in[jc] : b_hn[jc];
        sbias[a * 16 + i] = v;
    }
    const unsigned s1base = *(volatile unsigned*)&g_mt_cnt[255];
    __syncthreads();
    const unsigned gen0 = s_gen0;

    // pointwise ownership: col jcol, rows r2, r2+1
    const int c_pb = tid & 15;
    const int r2   = (tid >> 4) << 1;
    const int jcol = col0 + c_pb;

    float pg_r[2], pg_z[2], pg_n[2];
    float hpq[2] = {0.f, 0.f};

    if (tid == 1) {
        while ((int)(ld_acq(&g_mt_cnt[0]) - (s1base + 48u)) < 0) { }
    }
    __syncthreads();
#pragma unroll
    for (int q = 0; q < 2; q++) {
        size_t gi = (size_t)(r2 + q) * 1024 + jcol;
        pg_r[q] = g_gates[gi];
        pg_z[q] = g_gates[TBH + gi];
        pg_n[q] = g_gates[2ull * TBH + gi];
    }

    for (int t = 0; t < TSZ; t++) {
        if (t > 0) {
            // ===== Phase A: hW [64 x 48] = h_{t-1} @ [Whr|Whz|Whn] cols =====
            const float* hsrc = g_ht[(t - 1) & 1];

            wmma::fragment<wmma::accumulator, 16, 16, 8, float> acc[2][3];
#pragma unroll
            for (int mi = 0; mi < 2; mi++)
#pragma unroll
                for (int g = 0; g < 3; g++) wmma::fill_fragment(acc[mi][g], 0.0f);

#define R_ISSUE(c)                                                              \
            {                                                                   \
                int kofs = (c) * 16;                                            \
                _Pragma("unroll")                                               \
                for (int q = 0; q < 4; q++) {                                   \
                    int o = tid + q * 512;                                      \
                    int kg = o >> 8, idx = o & 255;                             \
                    int row = idx >> 2, c4 = (idx & 3) << 2;                    \
                    cp16(hb + (((c) & 1) * 8 + kg) * 1280 + row * 20 + c4,      \
                         hsrc + (size_t)row * 1024 + kg * 128 + kofs + c4);     \
                }                                                               \
                _Pragma("unroll")                                               \
                for (int q = 0; q < 3; q++) {                                   \
                    int o = tid + q * 512;                                      \
                    int kg = o / 192, idx = o % 192;                            \
                    int row = idx / 12, cw = (idx % 12) << 2;                   \
                    int gate = cw >> 4;                                         \
                    cp16(Wb + (((c) & 1) * 8 + kg) * 832 + row * 52 + cw,       \
                         g_Wall + (size_t)gate * 1048576                        \
                                + (size_t)(kg * 128 + kofs + row) * 1024        \
                                + col0 + (cw & 15));                            \
                }                                                               \
            }

            R_ISSUE(0); CP_COMMIT();

            for (int it = 0; it < 8; it++) {
                CP_WAIT0();
                __syncthreads();               // single sync per iteration
                if (it < 7) { R_ISSUE(it + 1); CP_COMMIT(); }

                const float* A = hb + ((it & 1) * 8 + kgrp) * 1280 + (mpair * 32) * 20;
                const float* B = Wb + ((it & 1) * 8 + kgrp) * 832;
#pragma unroll
                for (int kk = 0; kk < 2; kk++) {
                    wmma::fragment<wmma::matrix_a, 16, 16, 8, wmma::precision::tf32, wmma::row_major> a0, a1;
                    wmma::load_matrix_sync(a0, A + kk * 8, 20);
                    wmma::load_matrix_sync(a1, A + 16 * 20 + kk * 8, 20);
#pragma unroll
                    for (int g = 0; g < 3; g++) {
                        wmma::fragment<wmma::matrix_b, 16, 16, 8, wmma::precision::tf32, wmma::row_major> bf;
                        wmma::load_matrix_sync(bf, B + (kk * 8) * 52 + g * 16, 52);
                        wmma::mma_sync(acc[0][g], a0, bf, acc[0][g]);
                        wmma::mma_sync(acc[1][g], a1, bf, acc[1][g]);
                    }
                }
            }
#undef R_ISSUE

            // 8-way K reduction: kgrp 1..7 publish, kgrp 0 combines -> pre
            if (kgrp > 0) {
                float* s = red + (size_t)(kgrp - 1) * 3072;
#pragma unroll
                for (int mi = 0; mi < 2; mi++)
#pragma unroll
                    for (int g = 0; g < 3; g++)
                        wmma::store_matrix_sync(s + (mpair * 32 + mi * 16) * 48 + g * 16,
                                                acc[mi][g], 48, wmma::mem_row_major);
            }
            __syncthreads();
            if (kgrp == 0) {
#pragma unroll
                for (int src = 0; src < 7; src++) {
                    const float* s = red + (size_t)src * 3072;
#pragma unroll
                    for (int mi = 0; mi < 2; mi++)
#pragma unroll
                        for (int g = 0; g < 3; g++) {
                            wmma::fragment<wmma::accumulator, 16, 16, 8, float> p;
                            wmma::load_matrix_sync(p, s + (mpair * 32 + mi * 16) * 48 + g * 16,
                                                   48, wmma::mem_row_major);
#pragma unroll
                            for (int e = 0; e < p.num_elements; e++) acc[mi][g].x[e] += p.x[e];
                        }
                }
#pragma unroll
                for (int mi = 0; mi < 2; mi++)
#pragma unroll
                    for (int g = 0; g < 3; g++)
                        wmma::store_matrix_sync(pre + (mpair * 32 + mi * 16) * 48 + g * 16,
                                                acc[mi][g], 48, wmma::mem_row_major);
            }
            __syncthreads();
        }

        // ===== Phase B: pointwise =====
        {
            const size_t toff = (size_t)t * BH;
#pragma unroll
            for (int q = 0; q < 2; q++) {
                int row = r2 + q;
                float gr = pg_r[q] + sbias[c_pb];
                float gz = pg_z[q] + sbias[16 + c_pb];
                float gn = pg_n[q] + sbias[32 + c_pb];
                float hn = sbias[48 + c_pb];
                if (t > 0) {
                    gr += pre[row * 48 + c_pb];
                    gz += pre[row * 48 + 16 + c_pb];
                    hn += pre[row * 48 + 32 + c_pb];
                }
                float r = 1.0f / (1.0f + expf(-gr));
                float z = 1.0f / (1.0f + expf(-gz));
                float n = tanhf(gn + r * hn);
                float hnew = (1.0f - z) * n + z * hpq[q];
                hpq[q] = hnew;
                out[toff + (size_t)row * 1024 + jcol] = hnew;
                g_ht[t & 1][(size_t)row * 1024 + jcol] = wmma::__float_to_tf32(hnew);
                if (t == TSZ - 1 && write_hfinal)
                    out[TBH + (size_t)row * 1024 + jcol] = hnew;
            }
        }

        if (t == TSZ - 1) break;

        // ===== split grid barrier + stage1 poll + gate prefetch =====
        __syncthreads();
        const unsigned target = gen0 + (unsigned)t + 1u;
        bool released = false;
        if (tid == 0) {
            unsigned old;
            asm volatile("atom.acq_rel.gpu.add.u32 %0, [%1], %2;"
                         : "=r"(old) : "l"(&g_bar_cnt), "r"(1u) : "memory");
            if (old == NREC - 1u) {
                asm volatile("st.relaxed.gpu.u32 [%0], %1;" :: "l"(&g_bar_cnt), "r"(0u) : "memory");
                st_rel(&g_bar_gen, target);
                released = true;
            }
        }
        if (tid == 1) {                      // gates for t+1 produced?
            int mt = (t + 1) >> 1;
            while ((int)(ld_acq(&g_mt_cnt[mt]) - (s1base + 48u)) < 0) { }
        }
        __syncthreads();
        {
            const size_t toff1 = (size_t)(t + 1) * BH;
#pragma unroll
            for (int q = 0; q < 2; q++) {
                size_t gi = toff1 + (size_t)(r2 + q) * 1024 + jcol;
                pg_r[q] = g_gates[gi];
                pg_z[q] = g_gates[TBH + gi];
                pg_n[q] = g_gates[2ull * TBH + gi];
            }
        }
        if (tid == 0 && !released) {
            unsigned v;
            do {
                asm volatile("ld.acquire.gpu.u32 %0, [%1];" : "=r"(v) : "l"(&g_bar_gen) : "memory");
            } while ((int)(v - target) < 0);
        }
        __syncthreads();
    }
}

// ---------------------------------------------------------------------------
extern "C" void kernel_launch(void* const* d_in, const int* in_sizes, int n_in,
                              void* d_out, int out_size) {
    const float* x    = (const float*)d_in[0];
    const float* W_ir = (const float*)d_in[1];
    const float* b_ir = (const float*)d_in[2];
    const float* W_hr = (const float*)d_in[3];
    const float* b_hr = (const float*)d_in[4];
    const float* W_iz = (const float*)d_in[5];
    const float* b_iz = (const float*)d_in[6];
    const float* W_hz = (const float*)d_in[7];
    const float* b_hz = (const float*)d_in[8];
    const float* W_in = (const float*)d_in[9];
    const float* b_in = (const float*)d_in[10];
    const float* W_hn = (const float*)d_in[11];
    const float* b_hn = (const float*)d_in[12];
    float* out = (float*)d_out;

    const int has_hfinal = ((size_t)out_size >= TBH + (size_t)BH) ? 1 : 0;

    static bool init_done = false;
    if (!init_done) {
        cudaFuncSetAttribute(fused_kernel,
                             cudaFuncAttributeMaxDynamicSharedMemorySize, FUSED_SMEM);
        init_done = true;
    }

    prep_kernel<<<38912, 256>>>(x, W_hr, W_hz, W_hn, W_ir, W_iz, W_in);
    fused_kernel<<<NTOT, NTHR, FUSED_SMEM>>>(b_ir, b_hr, b_iz, b_hz, b_in, b_hn,
                                             out, has_hfinal);
}

// round 17
// speedup vs baseline: 1.5636x; 1.0077x over previous
#include <cuda_runtime.h>
#include <mma.h>
#include <math.h>
#include <stdint.h>

using namespace nvcuda;

#define TSZ   512
#define INSZ  1024
#define HIDSZ 1024
#define BH    65536                        // 64*1024
static constexpr size_t TBH = 33554432ull; // 512*64*1024

#define NREC  64                           // recurrence CTAs
#define NS1   80                           // stage1 worker CTAs
#define NTOT  144
#define NTHR  512

// Device-global scratch (no allocations allowed)
__device__ float g_gates[3ull * TBH];           // [gate][t*64+b][hid]
__device__ float g_Wall[6ull * 1048576];        // tf32 W: [hr|hz|hn|ir|iz|in]
__device__ float g_xt[32768ull * 1024];         // tf32 x, time-major [t*64+b][k]
__device__ float g_ht[2][BH];                   // tf32 h ping-pong
__device__ unsigned g_bar_cnt = 0;              // grid barrier (recur CTAs only)
__device__ unsigned g_bar_gen = 0;
__device__ unsigned g_mt_cnt[256];              // stage1 per-mtile counters (monotonic)

// ---------------------------------------------------------------------------
__device__ __forceinline__ unsigned ld_acq(const unsigned* p) {
    unsigned v;
    asm volatile("ld.acquire.gpu.u32 %0, [%1];" : "=r"(v) : "l"(p) : "memory");
    return v;
}
__device__ __forceinline__ void st_rel(unsigned* p, unsigned v) {
    asm volatile("st.release.gpu.u32 [%0], %1;" :: "l"(p), "r"(v) : "memory");
}
__device__ __forceinline__ void red_rel_add(unsigned* p) {
    asm volatile("red.release.gpu.global.add.u32 [%0], %1;" :: "l"(p), "r"(1u) : "memory");
}
__device__ __forceinline__ void cp16(void* sdst, const void* gsrc) {
    unsigned s;
    asm("{ .reg .u64 t; cvta.to.shared.u64 t, %1; cvt.u32.u64 %0, t; }" : "=r"(s) : "l"(sdst));
    asm volatile("cp.async.cg.shared.global [%0], [%1], 16;" :: "r"(s), "l"(gsrc));
}
#define CP_COMMIT() asm volatile("cp.async.commit_group;")
#define CP_WAIT0()  asm volatile("cp.async.wait_group 0;")
#define CP_WAIT1()  asm volatile("cp.async.wait_group 1;")

// ---------------------------------------------------------------------------
// Prep: tf32 weights -> g_Wall[0..5] (hr,hz,hn,ir,iz,in); x tf32 + transpose.
// ---------------------------------------------------------------------------
__global__ void prep_kernel(const float* __restrict__ x,
                            const float* __restrict__ Whr, const float* __restrict__ Whz,
                            const float* __restrict__ Whn, const float* __restrict__ Wir,
                            const float* __restrict__ Wiz, const float* __restrict__ Win) {
    const int bid = blockIdx.x, tid = threadIdx.x;
    if (bid < 6144) {
        int which = bid >> 10;
        int o = (bid & 1023) * 256 + tid;
        const float* src = (which == 0) ? Whr : (which == 1) ? Whz : (which == 2) ? Whn
                         : (which == 3) ? Wir : (which == 4) ? Wiz : Win;
        float4 v = ((const float4*)src)[o];
        v.x = wmma::__float_to_tf32(v.x); v.y = wmma::__float_to_tf32(v.y);
        v.z = wmma::__float_to_tf32(v.z); v.w = wmma::__float_to_tf32(v.w);
        ((float4*)(g_Wall + (size_t)which * 1048576))[o] = v;
    } else {
        int m = bid - 6144;                     // 0..32767, m = t*64+b
        int t = m >> 6, b = m & 63;
        float4 v = ((const float4*)(x + ((size_t)b * TSZ + t) * INSZ))[tid];
        v.x = wmma::__float_to_tf32(v.x); v.y = wmma::__float_to_tf32(v.y);
        v.z = wmma::__float_to_tf32(v.z); v.w = wmma::__float_to_tf32(v.w);
        ((float4*)(g_xt + (size_t)m * 1024))[tid] = v;
    }
}

// ---------------------------------------------------------------------------
// Fused persistent kernel, grid 144 x 512 — R16 champion; ONLY change:
// recurrence K-loop is a 3-stage lookahead pipeline (wait_group 1), so the
// group consumed at iteration it was issued at it-2 and has a full iteration
// to land. red/pre alias the (drained) stage buffers, with a guard sync.
// Recurrence smem (floats):
//   hb  @0      : 3 stages x 8 kgrp x [64][20]   (30720 fl)
//   Wb  @30720  : 3 stages x 8 kgrp x [16][52]   (19968 fl)
//   red alias @0     : 7 x [64][48] (21504 fl, post-loop, guard-synced)
//   pre alias @30720 : [64][48]     (3072 fl, post-combine)
//   bias@50688  : [4][16]
// Total 50752 fl = 203008 B. Stage1 path uses sm[0..13568).
// ---------------------------------------------------------------------------
#define FUSED_SMEM 203008

__global__ __launch_bounds__(NTHR, 1)
void fused_kernel(const float* __restrict__ b_ir, const float* __restrict__ b_hr,
                  const float* __restrict__ b_iz, const float* __restrict__ b_hz,
                  const float* __restrict__ b_in, const float* __restrict__ b_hn,
                  float* __restrict__ out, int write_hfinal) {
    extern __shared__ __align__(16) float sm[];
    const int cta = blockIdx.x;
    const int tid = threadIdx.x;
    const int wid = tid >> 5;

    if (cta >= NREC) {
        // ==================== STAGE1 WORKER (unchanged) ====================
        const int worker = cta - NREC;
        const int mrow = wid & 3;
        const int ncol = wid >> 2;

        for (int u = worker; u < 12288; u += NS1) {
            const int mtile = u / 48;
            const int sub   = u - mtile * 48;
            const int gate  = sub >> 4;
            const int col0s = (sub & 15) << 6;
            const int m0    = mtile << 7;
            const float* Wp = g_Wall + (size_t)(3 + gate) * 1048576;

            wmma::fragment<wmma::accumulator, 16, 16, 8, float> acc0, acc1;
            wmma::fill_fragment(acc0, 0.0f);
            wmma::fill_fragment(acc1, 0.0f);

#define S1_ISSUE(c)                                                             \
            {                                                                   \
                float* As = sm + ((c) & 1) * 6784;                              \
                float* Bs = As + 4608;                                          \
                _Pragma("unroll")                                               \
                for (int q = 0; q < 2; q++) {                                   \
                    int o = tid + q * 512;                                      \
                    int row = o >> 3, c4 = (o & 7) << 2;                        \
                    cp16(As + row * 36 + c4,                                    \
                         g_xt + (size_t)(m0 + row) * 1024 + (c) * 32 + c4);     \
                }                                                               \
                {                                                               \
                    int row = tid >> 4, c4 = (tid & 15) << 2;                   \
                    cp16(Bs + row * 68 + c4,                                    \
                         Wp + (size_t)((c) * 32 + row) * 1024 + col0s + c4);    \
                }                                                               \
            }

            S1_ISSUE(0); CP_COMMIT();
            for (int c = 0; c < 32; c++) {
                CP_WAIT0();
                __syncthreads();               // single sync per iteration
                if (c < 31) { S1_ISSUE(c + 1); CP_COMMIT(); }

                const float* As = sm + (c & 1) * 6784;
                const float* Bs = As + 4608;
#pragma unroll
                for (int kk = 0; kk < 4; kk++) {
                    wmma::fragment<wmma::matrix_a, 16, 16, 8, wmma::precision::tf32, wmma::row_major> a0, a1;
                    wmma::load_matrix_sync(a0, As + (mrow * 32) * 36 + kk * 8, 36);
                    wmma::load_matrix_sync(a1, As + (mrow * 32 + 16) * 36 + kk * 8, 36);
                    wmma::fragment<wmma::matrix_b, 16, 16, 8, wmma::precision::tf32, wmma::row_major> bf;
                    wmma::load_matrix_sync(bf, Bs + (kk * 8) * 68 + ncol * 16, 68);
                    wmma::mma_sync(acc0, a0, bf, acc0);
                    wmma::mma_sync(acc1, a1, bf, acc1);
                }
            }
#undef S1_ISSUE

            wmma::store_matrix_sync(
                g_gates + (size_t)gate * TBH + (size_t)(m0 + mrow * 32) * 1024 + col0s + ncol * 16,
                acc0, 1024, wmma::mem_row_major);
            wmma::store_matrix_sync(
                g_gates + (size_t)gate * TBH + (size_t)(m0 + mrow * 32 + 16) * 1024 + col0s + ncol * 16,
                acc1, 1024, wmma::mem_row_major);

            __syncthreads();
            if (tid == 0) red_rel_add(&g_mt_cnt[mtile]);
        }
        return;
    }

    // ==================== RECURRENCE ====================
    float* hb    = sm;                 // 3*8*[64][20]
    float* Wb    = sm + 30720;         // 3*8*[16][52]
    float* red   = sm;                 // 7*[64][48] alias (guard-synced)
    float* pre   = sm + 30720;         // [64][48] alias
    float* sbias = sm + 50688;         // [4][16]

    const int kgrp  = wid >> 1;          // 0..7, K range [kgrp*128, +128)
    const int mpair = wid & 1;           // rows [32*mpair, +32)
    const int col0  = cta << 4;

    __shared__ unsigned s_gen0;
    if (tid == 0) s_gen0 = *(volatile unsigned*)&g_bar_gen;
    if (tid < 64) {                      // [br_tot, bz_tot, b_in, b_hn][16]
        int a = tid >> 4, i = tid & 15, jc = col0 + i;
        float v = (a == 0) ? (b_ir[jc] + b_hr[jc])
                : (a == 1) ? (b_iz[jc] + b_hz[jc])
                : (a == 2) ? b_in[jc] : b_hn[jc];
        sbias[a * 16 + i] = v;
    }
    const unsigned s1base = *(volatile unsigned*)&g_mt_cnt[255];
    __syncthreads();
    const unsigned gen0 = s_gen0;

    // pointwise ownership: col jcol, rows r2, r2+1
    const int c_pb = tid & 15;
    const int r2   = (tid >> 4) << 1;
    const int jcol = col0 + c_pb;

    float pg_r[2], pg_z[2], pg_n[2];
    float hpq[2] = {0.f, 0.f};

    if (tid == 1) {
        while ((int)(ld_acq(&g_mt_cnt[0]) - (s1base + 48u)) < 0) { }
    }
    __syncthreads();
#pragma unroll
    for (int q = 0; q < 2; q++) {
        size_t gi = (size_t)(r2 + q) * 1024 + jcol;
        pg_r[q] = g_gates[gi];
        pg_z[q] = g_gates[TBH + gi];
        pg_n[q] = g_gates[2ull * TBH + gi];
    }

    for (int t = 0; t < TSZ; t++) {
        if (t > 0) {
            // ===== Phase A: hW [64 x 48], 3-stage lookahead pipeline =====
            const float* hsrc = g_ht[(t - 1) & 1];

            wmma::fragment<wmma::accumulator, 16, 16, 8, float> acc[2][3];
#pragma unroll
            for (int mi = 0; mi < 2; mi++)
#pragma unroll
                for (int g = 0; g < 3; g++) wmma::fill_fragment(acc[mi][g], 0.0f);

#define R_ISSUE(c)                                                              \
            {                                                                   \
                int kofs = (c) * 16;                                            \
                int stg  = (c) % 3;                                             \
                _Pragma("unroll")                                               \
                for (int q = 0; q < 4; q++) {                                   \
                    int o = tid + q * 512;                                      \
                    int kg = o >> 8, idx = o & 255;                             \
                    int row = idx >> 2, c4 = (idx & 3) << 2;                    \
                    cp16(hb + (stg * 8 + kg) * 1280 + row * 20 + c4,            \
                         hsrc + (size_t)row * 1024 + kg * 128 + kofs + c4);     \
                }                                                               \
                _Pragma("unroll")                                               \
                for (int q = 0; q < 3; q++) {                                   \
                    int o = tid + q * 512;                                      \
                    int kg = o / 192, idx = o % 192;                            \
                    int row = idx / 12, cw = (idx % 12) << 2;                   \
                    int gate = cw >> 4;                                         \
                    cp16(Wb + (stg * 8 + kg) * 832 + row * 52 + cw,             \
                         g_Wall + (size_t)gate * 1048576                        \
                                + (size_t)(kg * 128 + kofs + row) * 1024        \
                                + col0 + (cw & 15));                            \
                }                                                               \
            }

            R_ISSUE(0); CP_COMMIT();
            R_ISSUE(1); CP_COMMIT();

            for (int it = 0; it < 8; it++) {
                if (it < 7) { CP_WAIT1(); } else { CP_WAIT0(); }
                __syncthreads();               // orders compute(it-1) before issue(it+2)
                if (it < 6) { R_ISSUE(it + 2); CP_COMMIT(); }

                const float* A = hb + ((it % 3) * 8 + kgrp) * 1280 + (mpair * 32) * 20;
                const float* B = Wb + ((it % 3) * 8 + kgrp) * 832;
#pragma unroll
                for (int kk = 0; kk < 2; kk++) {
                    wmma::fragment<wmma::matrix_a, 16, 16, 8, wmma::precision::tf32, wmma::row_major> a0, a1;
                    wmma::load_matrix_sync(a0, A + kk * 8, 20);
                    wmma::load_matrix_sync(a1, A + 16 * 20 + kk * 8, 20);
#pragma unroll
                    for (int g = 0; g < 3; g++) {
                        wmma::fragment<wmma::matrix_b, 16, 16, 8, wmma::precision::tf32, wmma::row_major> bf;
                        wmma::load_matrix_sync(bf, B + (kk * 8) * 52 + g * 16, 52);
                        wmma::mma_sync(acc[0][g], a0, bf, acc[0][g]);
                        wmma::mma_sync(acc[1][g], a1, bf, acc[1][g]);
                    }
                }
            }
#undef R_ISSUE

            // guard: all warps done with stage buffers before red alias write
            __syncthreads();

            // 8-way K reduction: kgrp 1..7 publish, kgrp 0 combines -> pre
            if (kgrp > 0) {
                float* s = red + (size_t)(kgrp - 1) * 3072;
#pragma unroll
                for (int mi = 0; mi < 2; mi++)
#pragma unroll
                    for (int g = 0; g < 3; g++)
                        wmma::store_matrix_sync(s + (mpair * 32 + mi * 16) * 48 + g * 16,
                                                acc[mi][g], 48, wmma::mem_row_major);
            }
            __syncthreads();
            if (kgrp == 0) {
#pragma unroll
                for (int src = 0; src < 7; src++) {
                    const float* s = red + (size_t)src * 3072;
#pragma unroll
                    for (int mi = 0; mi < 2; mi++)
#pragma unroll
                        for (int g = 0; g < 3; g++) {
                            wmma::fragment<wmma::accumulator, 16, 16, 8, float> p;
                            wmma::load_matrix_sync(p, s + (mpair * 32 + mi * 16) * 48 + g * 16,
                                                   48, wmma::mem_row_major);
#pragma unroll
                            for (int e = 0; e < p.num_elements; e++) acc[mi][g].x[e] += p.x[e];
                        }
                }
#pragma unroll
                for (int mi = 0; mi < 2; mi++)
#pragma unroll
                    for (int g = 0; g < 3; g++)
                        wmma::store_matrix_sync(pre + (mpair * 32 + mi * 16) * 48 + g * 16,
                                                acc[mi][g], 48, wmma::mem_row_major);
            }
            __syncthreads();
        }

        // ===== Phase B: pointwise =====
        {
            const size_t toff = (size_t)t * BH;
#pragma unroll
            for (int q = 0; q < 2; q++) {
                int row = r2 + q;
                float gr = pg_r[q] + sbias[c_pb];
                float gz = pg_z[q] + sbias[16 + c_pb];
                float gn = pg_n[q] + sbias[32 + c_pb];
                float hn = sbias[48 + c_pb];
                if (t > 0) {
                    gr += pre[row * 48 + c_pb];
                    gz += pre[row * 48 + 16 + c_pb];
                    hn += pre[row * 48 + 32 + c_pb];
                }
                float r = 1.0f / (1.0f + expf(-gr));
                float z = 1.0f / (1.0f + expf(-gz));
                float n = tanhf(gn + r * hn);
                float hnew = (1.0f - z) * n + z * hpq[q];
                hpq[q] = hnew;
                out[toff + (size_t)row * 1024 + jcol] = hnew;
                g_ht[t & 1][(size_t)row * 1024 + jcol] = wmma::__float_to_tf32(hnew);
                if (t == TSZ - 1 && write_hfinal)
                    out[TBH + (size_t)row * 1024 + jcol] = hnew;
            }
        }

        if (t == TSZ - 1) break;

        // ===== split grid barrier + stage1 poll + gate prefetch =====
        __syncthreads();
        const unsigned target = gen0 + (unsigned)t + 1u;
        bool released = false;
        if (tid == 0) {
            unsigned old;
            asm volatile("atom.acq_rel.gpu.add.u32 %0, [%1], %2;"
                         : "=r"(old) : "l"(&g_bar_cnt), "r"(1u) : "memory");
            if (old == NREC - 1u) {
                asm volatile("st.relaxed.gpu.u32 [%0], %1;" :: "l"(&g_bar_cnt), "r"(0u) : "memory");
                st_rel(&g_bar_gen, target);
                released = true;
            }
        }
        if (tid == 1) {                      // gates for t+1 produced?
            int mt = (t + 1) >> 1;
            while ((int)(ld_acq(&g_mt_cnt[mt]) - (s1base + 48u)) < 0) { }
        }
        __syncthreads();
        {
            const size_t toff1 = (size_t)(t + 1) * BH;
#pragma unroll
            for (int q = 0; q < 2; q++) {
                size_t gi = toff1 + (size_t)(r2 + q) * 1024 + jcol;
                pg_r[q] = g_gates[gi];
                pg_z[q] = g_gates[TBH + gi];
                pg_n[q] = g_gates[2ull * TBH + gi];
            }
        }
        if (tid == 0 && !released) {
            unsigned v;
            do {
                asm volatile("ld.acquire.gpu.u32 %0, [%1];" : "=r"(v) : "l"(&g_bar_gen) : "memory");
            } while ((int)(v - target) < 0);
        }
        __syncthreads();
    }
}

// ---------------------------------------------------------------------------
extern "C" void kernel_launch(void* const* d_in, const int* in_sizes, int n_in,
                              void* d_out, int out_size) {
    const float* x    = (const float*)d_in[0];
    const float* W_ir = (const float*)d_in[1];
    const float* b_ir = (const float*)d_in[2];
    const float* W_hr = (const float*)d_in[3];
    const float* b_hr = (const float*)d_in[4];
    const float* W_iz = (const float*)d_in[5];
    const float* b_iz = (const float*)d_in[6];
    const float* W_hz = (const float*)d_in[7];
    const float* b_hz = (const float*)d_in[8];
    const float* W_in = (const float*)d_in[9];
    const float* b_in = (const float*)d_in[10];
    const float* W_hn = (const float*)d_in[11];
    const float* b_hn = (const float*)d_in[12];
    float* out = (float*)d_out;

    const int has_hfinal = ((size_t)out_size >= TBH + (size_t)BH) ? 1 : 0;

    static bool init_done = false;
    if (!init_done) {
        cudaFuncSetAttribute(fused_kernel,
                             cudaFuncAttributeMaxDynamicSharedMemorySize, FUSED_SMEM);
        init_done = true;
    }

    prep_kernel<<<38912, 256>>>(x, W_hr, W_hz, W_hn, W_ir, W_iz, W_in);
    fused_kernel<<<NTOT, NTHR, FUSED_SMEM>>>(b_ir, b_hr, b_iz, b_hz, b_in, b_hn,
                                             out, has_hfinal);
}